// round 2
// baseline (speedup 1.0000x reference)
#include <cuda_runtime.h>
#include <cuda_bf16.h>
#include <math.h>

#define BB 64       // batch
#define TT 32       // seq len
#define EE 512      // embed
#define HH 512      // hidden
#define GG 2048     // 4*H
#define VV 10000    // vocab

// ---------------- scratch (device globals; no allocation allowed) -------------
__device__ __align__(16) float g_xg[TT * BB * GG];    // [t][b][g]  16 MB
__device__ __align__(16) float g_hall[TT * BB * HH];  // [t][b][j]   4 MB
__device__ __align__(16) float g_hT[HH * BB];         // [j][b]  (k-major for step kernel)
__device__ __align__(16) float g_cT[HH * BB];         // [j][b]
__device__ int g_is64;

// ---------------- helpers ----------------------------------------------------
__global__ void init_state() {
    int i = blockIdx.x * blockDim.x + threadIdx.x;
    if (i < HH * BB) { g_hT[i] = 0.f; g_cT[i] = 0.f; }
}

// Detect whether captions buffer is int64 or int32.
// int64 little-endian values < 10000 => every odd int32 word is zero.
__global__ void detect_cap(const int* cap) {
    int nz = 0;
    for (int i = 1 + 2 * threadIdx.x; i < 2 * BB * TT; i += 2 * blockDim.x)
        nz |= (cap[i] != 0);
    nz = __syncthreads_or(nz);
    if (threadIdx.x == 0) g_is64 = (nz == 0);
}

// ---------------- GEMM 1: x_gates = gather(X) @ W_ih^T + b_ih + b_hh ----------
// C[m][n], m = t*64+b (m<2048), n<2048, K=512.  Tile 64x64x16, 256 thr, 4x4.
__global__ void __launch_bounds__(256) gemm_xg(
    const float* __restrict__ features,
    const void*  __restrict__ captions,
    const float* __restrict__ emb,
    const float* __restrict__ W_ih,
    const float* __restrict__ b_ih,
    const float* __restrict__ b_hh)
{
    __shared__ __align__(16) float As[16][68];
    __shared__ __align__(16) float Bs[16][68];

    const int m0 = blockIdx.y * 64;
    const int n0 = blockIdx.x * 64;
    const int tid = threadIdx.x;
    const int tx = tid & 15, ty = tid >> 4;

    // loader mapping: each thread loads one float4 of A and of B per k-chunk
    const int lrow = tid >> 2;      // 0..63
    const int lkq  = tid & 3;       // 0..3

    // A row pointer with fused gather
    const int m = m0 + lrow;
    const int t = m >> 6, b = m & 63;
    const float* arow;
    if (t == 0) {
        arow = features + (size_t)b * EE;
    } else {
        long long idx;
        if (g_is64) idx = ((const long long*)captions)[b * TT + (t - 1)];
        else        idx = ((const int*)captions)[b * TT + (t - 1)];
        arow = emb + (size_t)idx * EE;
    }
    const float* brow = W_ih + (size_t)(n0 + lrow) * EE;

    float acc[4][4] = {};

    for (int k0 = 0; k0 < EE; k0 += 16) {
        float4 av = *(const float4*)(arow + k0 + lkq * 4);
        float4 bv = *(const float4*)(brow + k0 + lkq * 4);
        __syncthreads();
        As[lkq * 4 + 0][lrow] = av.x; As[lkq * 4 + 1][lrow] = av.y;
        As[lkq * 4 + 2][lrow] = av.z; As[lkq * 4 + 3][lrow] = av.w;
        Bs[lkq * 4 + 0][lrow] = bv.x; Bs[lkq * 4 + 1][lrow] = bv.y;
        Bs[lkq * 4 + 2][lrow] = bv.z; Bs[lkq * 4 + 3][lrow] = bv.w;
        __syncthreads();
        #pragma unroll
        for (int kk = 0; kk < 16; kk++) {
            float4 a4 = *(const float4*)&As[kk][ty * 4];
            float4 b4 = *(const float4*)&Bs[kk][tx * 4];
            acc[0][0] += a4.x * b4.x; acc[0][1] += a4.x * b4.y; acc[0][2] += a4.x * b4.z; acc[0][3] += a4.x * b4.w;
            acc[1][0] += a4.y * b4.x; acc[1][1] += a4.y * b4.y; acc[1][2] += a4.y * b4.z; acc[1][3] += a4.y * b4.w;
            acc[2][0] += a4.z * b4.x; acc[2][1] += a4.z * b4.y; acc[2][2] += a4.z * b4.z; acc[2][3] += a4.z * b4.w;
            acc[3][0] += a4.w * b4.x; acc[3][1] += a4.w * b4.y; acc[3][2] += a4.w * b4.z; acc[3][3] += a4.w * b4.w;
        }
    }

    #pragma unroll
    for (int i = 0; i < 4; i++) {
        int mm = m0 + ty * 4 + i;
        #pragma unroll
        for (int j = 0; j < 4; j++) {
            int nn = n0 + tx * 4 + j;
            g_xg[(size_t)mm * GG + nn] = acc[i][j] + b_ih[nn] + b_hh[nn];
        }
    }
}

// ---------------- LSTM step (fused gates GEMM + nonlinearity) -----------------
// 128 CTAs; CTA handles hidden units j = jbase..jbase+3, all 4 gates, all 64 b.
// 256 threads; 2b x 2col register blocking over 16 gate-columns.
__global__ void __launch_bounds__(256) lstm_step(int t, const float* __restrict__ W_hh)
{
    __shared__ __align__(16) float ht[16][64];   // [kk][b]
    __shared__ __align__(16) float wt[16][16];   // [kk][cc]
    __shared__ float gs[16][65];                 // [cc][b]

    const int tid = threadIdx.x;
    const int jbase = blockIdx.x * 4;
    const int tb = tid & 31, tc = tid >> 5;
    const int b0 = tb * 2;
    const int cc0 = tc * 2;

    // column(cc) = gate*512 + jbase + jloc, gate = cc>>2, jloc = cc&3
    const int col0 = ((cc0) >> 2) * HH + jbase + ((cc0) & 3);
    const int col1 = ((cc0 + 1) >> 2) * HH + jbase + ((cc0 + 1) & 3);

    const float* xgt = g_xg + (size_t)t * BB * GG;
    float acc[2][2];
    acc[0][0] = xgt[(size_t)b0 * GG + col0];
    acc[0][1] = xgt[(size_t)b0 * GG + col1];
    acc[1][0] = xgt[(size_t)(b0 + 1) * GG + col0];
    acc[1][1] = xgt[(size_t)(b0 + 1) * GG + col1];

    for (int k0 = 0; k0 < HH; k0 += 16) {
        __syncthreads();
        for (int idx = tid; idx < 16 * 64; idx += 256) {
            int kk = idx >> 6, bb = idx & 63;
            ht[kk][bb] = g_hT[(size_t)(k0 + kk) * BB + bb];
        }
        {
            int cc = tid >> 4, kk = tid & 15;
            int row = (cc >> 2) * HH + jbase + (cc & 3);
            wt[kk][cc] = W_hh[(size_t)row * HH + k0 + kk];
        }
        __syncthreads();
        #pragma unroll
        for (int kk = 0; kk < 16; kk++) {
            float2 h2 = *(const float2*)&ht[kk][b0];
            float2 w2 = *(const float2*)&wt[kk][cc0];
            acc[0][0] += h2.x * w2.x; acc[0][1] += h2.x * w2.y;
            acc[1][0] += h2.y * w2.x; acc[1][1] += h2.y * w2.y;
        }
    }

    gs[cc0][b0]     = acc[0][0]; gs[cc0 + 1][b0]     = acc[0][1];
    gs[cc0][b0 + 1] = acc[1][0]; gs[cc0 + 1][b0 + 1] = acc[1][1];
    __syncthreads();

    // elementwise: thread -> (b, jloc)
    const int b = tid & 63, jl = tid >> 6;
    const float iv = gs[jl][b];
    const float fv = gs[4 + jl][b];
    const float gv = gs[8 + jl][b];
    const float ov = gs[12 + jl][b];
    const int j = jbase + jl;

    float c_old = g_cT[(size_t)j * BB + b];
    float si = 1.f / (1.f + expf(-iv));
    float sf = 1.f / (1.f + expf(-fv));
    float so = 1.f / (1.f + expf(-ov));
    float tg = tanhf(gv);
    float cn = sf * c_old + si * tg;
    float hn = so * tanhf(cn);
    g_cT[(size_t)j * BB + b] = cn;
    g_hT[(size_t)j * BB + b] = hn;
    g_hall[((size_t)t * BB + b) * HH + j] = hn;
}

// ---------------- GEMM 2: logits = h_all @ W_fc^T + b_fc ---------------------
// C[m][n], m = t*64+b (m<2048), n<10000, K=512. Output layout [b][t][v].
__global__ void __launch_bounds__(256) gemm_logits(
    const float* __restrict__ W_fc,
    const float* __restrict__ b_fc,
    float* __restrict__ out)
{
    __shared__ __align__(16) float As[16][68];
    __shared__ __align__(16) float Bs[16][68];

    const int m0 = blockIdx.y * 64;
    const int n0 = blockIdx.x * 64;
    const int tid = threadIdx.x;
    const int tx = tid & 15, ty = tid >> 4;
    const int lrow = tid >> 2;
    const int lkq  = tid & 3;

    const float* arow = g_hall + (size_t)(m0 + lrow) * HH;
    int nrow = n0 + lrow; if (nrow >= VV) nrow = VV - 1;   // clamp (stores guarded)
    const float* brow = W_fc + (size_t)nrow * HH;

    float acc[4][4] = {};

    for (int k0 = 0; k0 < HH; k0 += 16) {
        float4 av = *(const float4*)(arow + k0 + lkq * 4);
        float4 bv = *(const float4*)(brow + k0 + lkq * 4);
        __syncthreads();
        As[lkq * 4 + 0][lrow] = av.x; As[lkq * 4 + 1][lrow] = av.y;
        As[lkq * 4 + 2][lrow] = av.z; As[lkq * 4 + 3][lrow] = av.w;
        Bs[lkq * 4 + 0][lrow] = bv.x; Bs[lkq * 4 + 1][lrow] = bv.y;
        Bs[lkq * 4 + 2][lrow] = bv.z; Bs[lkq * 4 + 3][lrow] = bv.w;
        __syncthreads();
        #pragma unroll
        for (int kk = 0; kk < 16; kk++) {
            float4 a4 = *(const float4*)&As[kk][ty * 4];
            float4 b4 = *(const float4*)&Bs[kk][tx * 4];
            acc[0][0] += a4.x * b4.x; acc[0][1] += a4.x * b4.y; acc[0][2] += a4.x * b4.z; acc[0][3] += a4.x * b4.w;
            acc[1][0] += a4.y * b4.x; acc[1][1] += a4.y * b4.y; acc[1][2] += a4.y * b4.z; acc[1][3] += a4.y * b4.w;
            acc[2][0] += a4.z * b4.x; acc[2][1] += a4.z * b4.y; acc[2][2] += a4.z * b4.z; acc[2][3] += a4.z * b4.w;
            acc[3][0] += a4.w * b4.x; acc[3][1] += a4.w * b4.y; acc[3][2] += a4.w * b4.z; acc[3][3] += a4.w * b4.w;
        }
    }

    #pragma unroll
    for (int i = 0; i < 4; i++) {
        int mm = m0 + ty * 4 + i;
        int tt = mm >> 6, bb = mm & 63;
        size_t obase = ((size_t)bb * TT + tt) * VV;
        #pragma unroll
        for (int j = 0; j < 4; j++) {
            int nn = n0 + tx * 4 + j;
            if (nn < VV) out[obase + nn] = acc[i][j] + b_fc[nn];
        }
    }
}

// ---------------- launch ------------------------------------------------------
extern "C" void kernel_launch(void* const* d_in, const int* in_sizes, int n_in,
                              void* d_out, int out_size)
{
    const float* features = (const float*)d_in[0];
    const void*  captions = d_in[1];
    const float* emb      = (const float*)d_in[2];
    const float* W_ih     = (const float*)d_in[3];
    const float* W_hh     = (const float*)d_in[4];
    const float* b_ih     = (const float*)d_in[5];
    const float* b_hh     = (const float*)d_in[6];
    const float* W_fc     = (const float*)d_in[7];
    const float* b_fc     = (const float*)d_in[8];
    float* out = (float*)d_out;

    init_state<<<(HH * BB + 255) / 256, 256>>>();
    detect_cap<<<1, 256>>>((const int*)captions);

    gemm_xg<<<dim3(GG / 64, (TT * BB) / 64), 256>>>(features, captions, emb, W_ih, b_ih, b_hh);

    for (int t = 0; t < TT; t++)
        lstm_step<<<HH / 4, 256>>>(t, W_hh);

    gemm_logits<<<dim3((VV + 63) / 64, (TT * BB) / 64), 256>>>(W_fc, b_fc, out);
}

// round 5
// speedup vs baseline: 1.9733x; 1.9733x over previous
#include <cuda_runtime.h>
#include <cuda_bf16.h>
#include <math.h>

#define BB 64       // batch
#define TT 32       // seq len
#define EE 512      // embed
#define HH 512      // hidden
#define GG 2048     // 4*H
#define VV 10000    // vocab

// ---------------- scratch (device globals; no allocation allowed) -------------
__device__ __align__(16) float g_xg[TT * BB * GG];    // [t*64+b][g]  16 MB
__device__ __align__(16) float g_hall[TT * BB * HH];  // [t*64+b][j]   4 MB
__device__ __align__(16) float g_h[2][HH * BB];       // double-buffered h, [j][b]
__device__ __align__(16) float g_c[HH * BB];          // cell state [j][b]
__device__ int g_is64;

// ---------------- helpers ----------------------------------------------------
__global__ void init_state() {
    int i = blockIdx.x * blockDim.x + threadIdx.x;
    if (i < HH * BB) { g_h[0][i] = 0.f; g_c[i] = 0.f; }
}

// Detect whether captions buffer is int64 or int32 on device.
__global__ void detect_cap(const int* cap) {
    int nz = 0;
    for (int i = 1 + 2 * threadIdx.x; i < 2 * BB * TT; i += 2 * blockDim.x)
        nz |= (cap[i] != 0);
    nz = __syncthreads_or(nz);
    if (threadIdx.x == 0) g_is64 = (nz == 0);
}

__device__ __forceinline__ void cp16(void* smem, const void* gmem) {
    unsigned s = (unsigned)__cvta_generic_to_shared(smem);
    asm volatile("cp.async.ca.shared.global [%0], [%1], 16;" :: "r"(s), "l"(gmem));
}
__device__ __forceinline__ void cp_commit() {
    asm volatile("cp.async.commit_group;");
}
template <int N>
__device__ __forceinline__ void cp_wait() {
    asm volatile("cp.async.wait_group %0;" :: "n"(N));
}

// ---------------- GEMM 1: x_gates = gather(X) @ W_ih^T + b_ih + b_hh ----------
__global__ void __launch_bounds__(256) gemm_xg(
    const float* __restrict__ features,
    const void*  __restrict__ captions,
    const float* __restrict__ emb,
    const float* __restrict__ W_ih,
    const float* __restrict__ b_ih,
    const float* __restrict__ b_hh)
{
    __shared__ __align__(16) float As[16][68];
    __shared__ __align__(16) float Bs[16][68];

    const int m0 = blockIdx.y * 64;
    const int n0 = blockIdx.x * 64;
    const int tid = threadIdx.x;
    const int tx = tid & 15, ty = tid >> 4;
    const int lrow = tid >> 2;
    const int lkq  = tid & 3;

    const int m = m0 + lrow;
    const int t = m >> 6, b = m & 63;
    const float* arow;
    if (t == 0) {
        arow = features + (size_t)b * EE;
    } else {
        long long idx;
        if (g_is64) idx = ((const long long*)captions)[b * TT + (t - 1)];
        else        idx = ((const int*)captions)[b * TT + (t - 1)];
        arow = emb + (size_t)idx * EE;
    }
    const float* brow = W_ih + (size_t)(n0 + lrow) * EE;

    float acc[4][4] = {};

    for (int k0 = 0; k0 < EE; k0 += 16) {
        float4 av = *(const float4*)(arow + k0 + lkq * 4);
        float4 bv = *(const float4*)(brow + k0 + lkq * 4);
        __syncthreads();
        As[lkq * 4 + 0][lrow] = av.x; As[lkq * 4 + 1][lrow] = av.y;
        As[lkq * 4 + 2][lrow] = av.z; As[lkq * 4 + 3][lrow] = av.w;
        Bs[lkq * 4 + 0][lrow] = bv.x; Bs[lkq * 4 + 1][lrow] = bv.y;
        Bs[lkq * 4 + 2][lrow] = bv.z; Bs[lkq * 4 + 3][lrow] = bv.w;
        __syncthreads();
        #pragma unroll
        for (int kk = 0; kk < 16; kk++) {
            float4 a4 = *(const float4*)&As[kk][ty * 4];
            float4 b4 = *(const float4*)&Bs[kk][tx * 4];
            acc[0][0] += a4.x * b4.x; acc[0][1] += a4.x * b4.y; acc[0][2] += a4.x * b4.z; acc[0][3] += a4.x * b4.w;
            acc[1][0] += a4.y * b4.x; acc[1][1] += a4.y * b4.y; acc[1][2] += a4.y * b4.z; acc[1][3] += a4.y * b4.w;
            acc[2][0] += a4.z * b4.x; acc[2][1] += a4.z * b4.y; acc[2][2] += a4.z * b4.z; acc[2][3] += a4.z * b4.w;
            acc[3][0] += a4.w * b4.x; acc[3][1] += a4.w * b4.y; acc[3][2] += a4.w * b4.z; acc[3][3] += a4.w * b4.w;
        }
    }

    #pragma unroll
    for (int i = 0; i < 4; i++) {
        int mm = m0 + ty * 4 + i;
        #pragma unroll
        for (int j = 0; j < 4; j++) {
            int nn = n0 + tx * 4 + j;
            g_xg[(size_t)mm * GG + nn] = acc[i][j] + b_ih[nn] + b_hh[nn];
        }
    }
}

// ---------------- LSTM step: latency-hidden per-step kernel -------------------
// 128 CTAs x 256 thr. CTA owns 16 gate-cols (4 gates x 4 hidden units jbase..+3)
// and all 64 batches. h staged in 2x16KB smem chunks via cp.async double buffer.
// Thread tile: 1 col x 4 batches (LDS.128 + 4 FFMA per k). W via __ldg float4.
__global__ void __launch_bounds__(256) lstm_step(int t, const float* __restrict__ W_hh)
{
    __shared__ __align__(16) float hs[2][64 * 64];   // [buf][k][b]
    __shared__ __align__(16) float gsh[16 * 68];     // [cc][b]

    const int tid = threadIdx.x;
    const int jbase = blockIdx.x * 4;
    const int tc = tid >> 4;             // 0..15 -> gate col
    const int tb = tid & 15;             // b quad
    const int b0 = tb * 4;
    const int col = (tc >> 2) * HH + jbase + (tc & 3);
    const float* __restrict__ wrow = W_hh + (size_t)col * HH;

    const float* __restrict__ hin  = g_h[t & 1];
    float* __restrict__ hout = g_h[(t + 1) & 1];
    const float* __restrict__ xgt  = g_xg + (size_t)t * BB * GG;

    // accumulators init from x-gates
    float acc0 = xgt[(size_t)(b0 + 0) * GG + col];
    float acc1 = xgt[(size_t)(b0 + 1) * GG + col];
    float acc2 = xgt[(size_t)(b0 + 2) * GG + col];
    float acc3 = xgt[(size_t)(b0 + 3) * GG + col];

    // stage chunk 0
    #pragma unroll
    for (int r = 0; r < 4; r++) {
        int f = tid + r * 256;
        int k = f >> 4, bq = f & 15;
        cp16(&hs[0][k * 64 + bq * 4], &hin[(size_t)k * BB + bq * 4]);
    }
    cp_commit();

    #pragma unroll
    for (int kc = 0; kc < 8; kc++) {
        if (kc < 7) {
            #pragma unroll
            for (int r = 0; r < 4; r++) {
                int f = tid + r * 256;
                int k = f >> 4, bq = f & 15;
                cp16(&hs[(kc + 1) & 1][k * 64 + bq * 4],
                     &hin[(size_t)((kc + 1) * 64 + k) * BB + bq * 4]);
            }
            cp_commit();
            cp_wait<1>();
        } else {
            cp_wait<0>();
        }
        __syncthreads();

        const float* hc = hs[kc & 1];
        const float* wc = wrow + kc * 64;
        #pragma unroll
        for (int k4 = 0; k4 < 16; k4++) {
            float4 w4 = __ldg((const float4*)(wc + k4 * 4));
            {
                float4 h4 = *(const float4*)&hc[(k4 * 4 + 0) * 64 + b0];
                acc0 += h4.x * w4.x; acc1 += h4.y * w4.x; acc2 += h4.z * w4.x; acc3 += h4.w * w4.x;
            }
            {
                float4 h4 = *(const float4*)&hc[(k4 * 4 + 1) * 64 + b0];
                acc0 += h4.x * w4.y; acc1 += h4.y * w4.y; acc2 += h4.z * w4.y; acc3 += h4.w * w4.y;
            }
            {
                float4 h4 = *(const float4*)&hc[(k4 * 4 + 2) * 64 + b0];
                acc0 += h4.x * w4.z; acc1 += h4.y * w4.z; acc2 += h4.z * w4.z; acc3 += h4.w * w4.z;
            }
            {
                float4 h4 = *(const float4*)&hc[(k4 * 4 + 3) * 64 + b0];
                acc0 += h4.x * w4.w; acc1 += h4.y * w4.w; acc2 += h4.z * w4.w; acc3 += h4.w * w4.w;
            }
        }
        __syncthreads();
    }

    // stage gates [cc][b]
    *(float4*)&gsh[tc * 68 + b0] = make_float4(acc0, acc1, acc2, acc3);
    __syncthreads();

    // nonlinearity: thread -> (bnl, jl); cc = gate*4 + jl
    const int bnl = tid & 63, jl = tid >> 6;
    const float iv = gsh[(0  + jl) * 68 + bnl];
    const float fv = gsh[(4  + jl) * 68 + bnl];
    const float gv = gsh[(8  + jl) * 68 + bnl];
    const float ov = gsh[(12 + jl) * 68 + bnl];
    const int j = jbase + jl;

    float c_old = g_c[(size_t)j * BB + bnl];
    float si = 1.f / (1.f + expf(-iv));
    float sf = 1.f / (1.f + expf(-fv));
    float so = 1.f / (1.f + expf(-ov));
    float tg = tanhf(gv);
    float cn = sf * c_old + si * tg;
    float hn = so * tanhf(cn);
    g_c[(size_t)j * BB + bnl] = cn;
    hout[(size_t)j * BB + bnl] = hn;
    g_hall[((size_t)t * BB + bnl) * HH + j] = hn;
}

// ---------------- GEMM 2: logits = h_all @ W_fc^T + b_fc (128x64 tile) -------
__global__ void __launch_bounds__(256) gemm_logits(
    const float* __restrict__ W_fc,
    const float* __restrict__ b_fc,
    float* __restrict__ out)
{
    __shared__ __align__(16) float As[16][132];
    __shared__ __align__(16) float Bs[16][68];

    const int m0 = blockIdx.y * 128;
    const int n0 = blockIdx.x * 64;
    const int tid = threadIdx.x;
    const int tx = tid & 15, ty = tid >> 4;

    const int lrow = tid >> 2;      // 0..63
    const int lkq  = tid & 3;

    const float* a0p = g_hall + (size_t)(m0 + lrow) * HH + lkq * 4;
    const float* a1p = g_hall + (size_t)(m0 + lrow + 64) * HH + lkq * 4;
    int nb = n0 + lrow; if (nb >= VV) nb = VV - 1;
    const float* bp = W_fc + (size_t)nb * HH + lkq * 4;

    float acc[8][4] = {};

    for (int k0 = 0; k0 < HH; k0 += 16) {
        float4 av0 = *(const float4*)(a0p + k0);
        float4 av1 = *(const float4*)(a1p + k0);
        float4 bv  = *(const float4*)(bp + k0);
        __syncthreads();
        As[lkq * 4 + 0][lrow] = av0.x; As[lkq * 4 + 1][lrow] = av0.y;
        As[lkq * 4 + 2][lrow] = av0.z; As[lkq * 4 + 3][lrow] = av0.w;
        As[lkq * 4 + 0][lrow + 64] = av1.x; As[lkq * 4 + 1][lrow + 64] = av1.y;
        As[lkq * 4 + 2][lrow + 64] = av1.z; As[lkq * 4 + 3][lrow + 64] = av1.w;
        Bs[lkq * 4 + 0][lrow] = bv.x; Bs[lkq * 4 + 1][lrow] = bv.y;
        Bs[lkq * 4 + 2][lrow] = bv.z; Bs[lkq * 4 + 3][lrow] = bv.w;
        __syncthreads();
        #pragma unroll
        for (int kk = 0; kk < 16; kk++) {
            float4 a0 = *(const float4*)&As[kk][ty * 8];
            float4 a1 = *(const float4*)&As[kk][ty * 8 + 4];
            float4 b4 = *(const float4*)&Bs[kk][tx * 4];
            acc[0][0] += a0.x * b4.x; acc[0][1] += a0.x * b4.y; acc[0][2] += a0.x * b4.z; acc[0][3] += a0.x * b4.w;
            acc[1][0] += a0.y * b4.x; acc[1][1] += a0.y * b4.y; acc[1][2] += a0.y * b4.z; acc[1][3] += a0.y * b4.w;
            acc[2][0] += a0.z * b4.x; acc[2][1] += a0.z * b4.y; acc[2][2] += a0.z * b4.z; acc[2][3] += a0.z * b4.w;
            acc[3][0] += a0.w * b4.x; acc[3][1] += a0.w * b4.y; acc[3][2] += a0.w * b4.z; acc[3][3] += a0.w * b4.w;
            acc[4][0] += a1.x * b4.x; acc[4][1] += a1.x * b4.y; acc[4][2] += a1.x * b4.z; acc[4][3] += a1.x * b4.w;
            acc[5][0] += a1.y * b4.x; acc[5][1] += a1.y * b4.y; acc[5][2] += a1.y * b4.z; acc[5][3] += a1.y * b4.w;
            acc[6][0] += a1.z * b4.x; acc[6][1] += a1.z * b4.y; acc[6][2] += a1.z * b4.z; acc[6][3] += a1.z * b4.w;
            acc[7][0] += a1.w * b4.x; acc[7][1] += a1.w * b4.y; acc[7][2] += a1.w * b4.z; acc[7][3] += a1.w * b4.w;
        }
    }

    float bf[4];
    #pragma unroll
    for (int j = 0; j < 4; j++) {
        int nn = n0 + tx * 4 + j;
        bf[j] = (nn < VV) ? b_fc[nn] : 0.f;
    }
    #pragma unroll
    for (int i = 0; i < 8; i++) {
        int mm = m0 + ty * 8 + i;
        int tt = mm >> 6, bb = mm & 63;
        size_t obase = ((size_t)bb * TT + tt) * VV;
        #pragma unroll
        for (int j = 0; j < 4; j++) {
            int nn = n0 + tx * 4 + j;
            if (nn < VV) out[obase + nn] = acc[i][j] + bf[j];
        }
    }
}

// ---------------- launch ------------------------------------------------------
extern "C" void kernel_launch(void* const* d_in, const int* in_sizes, int n_in,
                              void* d_out, int out_size)
{
    const float* features = (const float*)d_in[0];
    const void*  captions = d_in[1];
    const float* emb      = (const float*)d_in[2];
    const float* W_ih     = (const float*)d_in[3];
    const float* W_hh     = (const float*)d_in[4];
    const float* b_ih     = (const float*)d_in[5];
    const float* b_hh     = (const float*)d_in[6];
    const float* W_fc     = (const float*)d_in[7];
    const float* b_fc     = (const float*)d_in[8];
    float* out = (float*)d_out;

    init_state<<<(HH * BB + 255) / 256, 256>>>();
    detect_cap<<<1, 256>>>((const int*)captions);

    gemm_xg<<<dim3(GG / 64, (TT * BB) / 64), 256>>>(features, captions, emb, W_ih, b_ih, b_hh);

    for (int t = 0; t < TT; t++)
        lstm_step<<<HH / 4, 256>>>(t, W_hh);

    gemm_logits<<<dim3((VV + 63) / 64, (TT * BB) / 128), 256>>>(W_fc, b_fc, out);
}

// round 13
// speedup vs baseline: 2.1457x; 1.0874x over previous
#include <cuda_runtime.h>
#include <cuda_bf16.h>
#include <math.h>

#define BB 64       // batch
#define TT 32       // seq len
#define EE 512      // embed
#define HH 512      // hidden
#define GG 2048     // 4*H
#define VV 10000    // vocab
#define MM 2048     // rows = TT*BB

// ---------------- scratch (device globals; no allocation allowed) -------------
__device__ __align__(16) float g_xg[MM * GG];         // [m][g]  16 MB
__device__ __align__(16) float g_hall[MM * HH];       // [m][j]   4 MB
__device__ __align__(16) float g_h[2][HH * BB];       // double-buffered h, [j][b]
__device__ __align__(16) float g_c[HH * BB];          // cell state [j][b]
__device__ int g_is64;

// ---------------- helpers ----------------------------------------------------
__global__ void init_state() {
    int i = blockIdx.x * blockDim.x + threadIdx.x;
    if (i < HH * BB) { g_h[0][i] = 0.f; g_c[i] = 0.f; }
}

// Detect whether captions buffer is int64 or int32 on device.
__global__ void detect_cap(const int* cap) {
    int nz = 0;
    for (int i = 1 + 2 * threadIdx.x; i < 2 * BB * TT; i += 2 * blockDim.x)
        nz |= (cap[i] != 0);
    nz = __syncthreads_or(nz);
    if (threadIdx.x == 0) g_is64 = (nz == 0);
}

__device__ __forceinline__ void cp16(void* smem, const void* gmem) {
    unsigned s = (unsigned)__cvta_generic_to_shared(smem);
    asm volatile("cp.async.ca.shared.global [%0], [%1], 16;" :: "r"(s), "l"(gmem));
}
__device__ __forceinline__ void cp_commit() { asm volatile("cp.async.commit_group;"); }
template <int N>
__device__ __forceinline__ void cp_wait() { asm volatile("cp.async.wait_group %0;" :: "n"(N)); }

// ---------------- GEMM 1: x_gates (fp32, PROVEN R5 code) ----------------------
__global__ void __launch_bounds__(256) gemm_xg(
    const float* __restrict__ features,
    const void*  __restrict__ captions,
    const float* __restrict__ emb,
    const float* __restrict__ W_ih,
    const float* __restrict__ b_ih,
    const float* __restrict__ b_hh)
{
    __shared__ __align__(16) float As[16][68];
    __shared__ __align__(16) float Bs[16][68];

    const int m0 = blockIdx.y * 64;
    const int n0 = blockIdx.x * 64;
    const int tid = threadIdx.x;
    const int tx = tid & 15, ty = tid >> 4;
    const int lrow = tid >> 2;
    const int lkq  = tid & 3;

    const int m = m0 + lrow;
    const int t = m >> 6, b = m & 63;
    const float* arow;
    if (t == 0) {
        arow = features + (size_t)b * EE;
    } else {
        long long idx;
        if (g_is64) idx = ((const long long*)captions)[b * TT + (t - 1)];
        else        idx = ((const int*)captions)[b * TT + (t - 1)];
        arow = emb + (size_t)idx * EE;
    }
    const float* brow = W_ih + (size_t)(n0 + lrow) * EE;

    float acc[4][4] = {};

    for (int k0 = 0; k0 < EE; k0 += 16) {
        float4 av = *(const float4*)(arow + k0 + lkq * 4);
        float4 bv = *(const float4*)(brow + k0 + lkq * 4);
        __syncthreads();
        As[lkq * 4 + 0][lrow] = av.x; As[lkq * 4 + 1][lrow] = av.y;
        As[lkq * 4 + 2][lrow] = av.z; As[lkq * 4 + 3][lrow] = av.w;
        Bs[lkq * 4 + 0][lrow] = bv.x; Bs[lkq * 4 + 1][lrow] = bv.y;
        Bs[lkq * 4 + 2][lrow] = bv.z; Bs[lkq * 4 + 3][lrow] = bv.w;
        __syncthreads();
        #pragma unroll
        for (int kk = 0; kk < 16; kk++) {
            float4 a4 = *(const float4*)&As[kk][ty * 4];
            float4 b4 = *(const float4*)&Bs[kk][tx * 4];
            acc[0][0] += a4.x * b4.x; acc[0][1] += a4.x * b4.y; acc[0][2] += a4.x * b4.z; acc[0][3] += a4.x * b4.w;
            acc[1][0] += a4.y * b4.x; acc[1][1] += a4.y * b4.y; acc[1][2] += a4.y * b4.z; acc[1][3] += a4.y * b4.w;
            acc[2][0] += a4.z * b4.x; acc[2][1] += a4.z * b4.y; acc[2][2] += a4.z * b4.z; acc[2][3] += a4.z * b4.w;
            acc[3][0] += a4.w * b4.x; acc[3][1] += a4.w * b4.y; acc[3][2] += a4.w * b4.z; acc[3][3] += a4.w * b4.w;
        }
    }

    #pragma unroll
    for (int i = 0; i < 4; i++) {
        int mm = m0 + ty * 4 + i;
        #pragma unroll
        for (int j = 0; j < 4; j++) {
            int nn = n0 + tx * 4 + j;
            g_xg[(size_t)mm * GG + nn] = acc[i][j] + b_ih[nn] + b_hh[nn];
        }
    }
}

// ---------------- LSTM step: R5 structure + W staged through smem -------------
// ONLY change vs the proven R5 kernel: the 4KB W chunk is cp.async
// double-buffered into smem together with h (1 extra cp16/thread/chunk).
// Inner loop is pure LDS+FFMA (no more per-k4 L2 __ldg on the critical path).
__global__ void __launch_bounds__(256) lstm_step(int t, const float* __restrict__ W_hh)
{
    __shared__ __align__(16) float hs[2][64 * 64];   // 32 KB
    __shared__ __align__(16) float ws[2][16 * 68];   // 8.5 KB  (row stride 272B)
    __shared__ __align__(16) float gsh[16 * 68];     // 4.25 KB

    const int tid = threadIdx.x;
    const int jbase = blockIdx.x * 4;
    const int tc = tid >> 4;             // 0..15 -> gate col
    const int tb = tid & 15;             // b quad / W k-quad
    const int b0 = tb * 4;
    const int col = (tc >> 2) * HH + jbase + (tc & 3);
    const float* __restrict__ wsrc = W_hh + (size_t)col * HH;

    const float* __restrict__ hin  = g_h[t & 1];
    float* __restrict__ hout = g_h[(t + 1) & 1];
    const float* __restrict__ xgt  = g_xg + (size_t)t * BB * GG;

    float acc0 = xgt[(size_t)(b0 + 0) * GG + col];
    float acc1 = xgt[(size_t)(b0 + 1) * GG + col];
    float acc2 = xgt[(size_t)(b0 + 2) * GG + col];
    float acc3 = xgt[(size_t)(b0 + 3) * GG + col];

    // prefetch chunk 0 (h + W)
    #pragma unroll
    for (int r = 0; r < 4; r++) {
        int f = tid + r * 256;
        int k = f >> 4, bq = f & 15;
        cp16(&hs[0][k * 64 + bq * 4], &hin[(size_t)k * BB + bq * 4]);
    }
    cp16(&ws[0][tc * 68 + tb * 4], wsrc + tb * 4);
    cp_commit();

    #pragma unroll
    for (int kc = 0; kc < 8; kc++) {
        if (kc < 7) {
            #pragma unroll
            for (int r = 0; r < 4; r++) {
                int f = tid + r * 256;
                int k = f >> 4, bq = f & 15;
                cp16(&hs[(kc + 1) & 1][k * 64 + bq * 4],
                     &hin[(size_t)((kc + 1) * 64 + k) * BB + bq * 4]);
            }
            cp16(&ws[(kc + 1) & 1][tc * 68 + tb * 4], wsrc + (kc + 1) * 64 + tb * 4);
            cp_commit();
            cp_wait<1>();
        } else {
            cp_wait<0>();
        }
        __syncthreads();

        const float* hc = hs[kc & 1];
        const float* wcp = &ws[kc & 1][tc * 68];
        #pragma unroll
        for (int k4 = 0; k4 < 16; k4++) {
            float4 w4 = *(const float4*)&wcp[k4 * 4];
            {
                float4 h4 = *(const float4*)&hc[(k4 * 4 + 0) * 64 + b0];
                acc0 += h4.x * w4.x; acc1 += h4.y * w4.x; acc2 += h4.z * w4.x; acc3 += h4.w * w4.x;
            }
            {
                float4 h4 = *(const float4*)&hc[(k4 * 4 + 1) * 64 + b0];
                acc0 += h4.x * w4.y; acc1 += h4.y * w4.y; acc2 += h4.z * w4.y; acc3 += h4.w * w4.y;
            }
            {
                float4 h4 = *(const float4*)&hc[(k4 * 4 + 2) * 64 + b0];
                acc0 += h4.x * w4.z; acc1 += h4.y * w4.z; acc2 += h4.z * w4.z; acc3 += h4.w * w4.z;
            }
            {
                float4 h4 = *(const float4*)&hc[(k4 * 4 + 3) * 64 + b0];
                acc0 += h4.x * w4.w; acc1 += h4.y * w4.w; acc2 += h4.z * w4.w; acc3 += h4.w * w4.w;
            }
        }
        __syncthreads();
    }

    *(float4*)&gsh[tc * 68 + b0] = make_float4(acc0, acc1, acc2, acc3);
    __syncthreads();

    const int bnl = tid & 63, jl = tid >> 6;
    const float iv = gsh[(0  + jl) * 68 + bnl];
    const float fv = gsh[(4  + jl) * 68 + bnl];
    const float gv = gsh[(8  + jl) * 68 + bnl];
    const float ov = gsh[(12 + jl) * 68 + bnl];
    const int j = jbase + jl;

    float c_old = g_c[(size_t)j * BB + bnl];
    float si = 1.f / (1.f + expf(-iv));
    float sf = 1.f / (1.f + expf(-fv));
    float so = 1.f / (1.f + expf(-ov));
    float tg = tanhf(gv);
    float cn = sf * c_old + si * tg;
    float hn = so * tanhf(cn);
    g_c[(size_t)j * BB + bnl] = cn;
    hout[(size_t)j * BB + bnl] = hn;
    g_hall[((size_t)t * BB + bnl) * HH + j] = hn;
}

// ---------------- GEMM 2: logits fp32 128x64 (PROVEN R5 code) -----------------
__global__ void __launch_bounds__(256) gemm_logits(
    const float* __restrict__ W_fc,
    const float* __restrict__ b_fc,
    float* __restrict__ out)
{
    __shared__ __align__(16) float As[16][132];
    __shared__ __align__(16) float Bs[16][68];

    const int m0 = blockIdx.y * 128;
    const int n0 = blockIdx.x * 64;
    const int tid = threadIdx.x;
    const int tx = tid & 15, ty = tid >> 4;
    const int lrow = tid >> 2;
    const int lkq  = tid & 3;

    const float* a0p = g_hall + (size_t)(m0 + lrow) * HH + lkq * 4;
    const float* a1p = g_hall + (size_t)(m0 + lrow + 64) * HH + lkq * 4;
    int nb = n0 + lrow; if (nb >= VV) nb = VV - 1;
    const float* bp = W_fc + (size_t)nb * HH + lkq * 4;

    float acc[8][4] = {};

    for (int k0 = 0; k0 < HH; k0 += 16) {
        float4 av0 = *(const float4*)(a0p + k0);
        float4 av1 = *(const float4*)(a1p + k0);
        float4 bv  = *(const float4*)(bp + k0);
        __syncthreads();
        As[lkq * 4 + 0][lrow] = av0.x; As[lkq * 4 + 1][lrow] = av0.y;
        As[lkq * 4 + 2][lrow] = av0.z; As[lkq * 4 + 3][lrow] = av0.w;
        As[lkq * 4 + 0][lrow + 64] = av1.x; As[lkq * 4 + 1][lrow + 64] = av1.y;
        As[lkq * 4 + 2][lrow + 64] = av1.z; As[lkq * 4 + 3][lrow + 64] = av1.w;
        Bs[lkq * 4 + 0][lrow] = bv.x; Bs[lkq * 4 + 1][lrow] = bv.y;
        Bs[lkq * 4 + 2][lrow] = bv.z; Bs[lkq * 4 + 3][lrow] = bv.w;
        __syncthreads();
        #pragma unroll
        for (int kk = 0; kk < 16; kk++) {
            float4 a0 = *(const float4*)&As[kk][ty * 8];
            float4 a1 = *(const float4*)&As[kk][ty * 8 + 4];
            float4 b4 = *(const float4*)&Bs[kk][tx * 4];
            acc[0][0] += a0.x * b4.x; acc[0][1] += a0.x * b4.y; acc[0][2] += a0.x * b4.z; acc[0][3] += a0.x * b4.w;
            acc[1][0] += a0.y * b4.x; acc[1][1] += a0.y * b4.y; acc[1][2] += a0.y * b4.z; acc[1][3] += a0.y * b4.w;
            acc[2][0] += a0.z * b4.x; acc[2][1] += a0.z * b4.y; acc[2][2] += a0.z * b4.z; acc[2][3] += a0.z * b4.w;
            acc[3][0] += a0.w * b4.x; acc[3][1] += a0.w * b4.y; acc[3][2] += a0.w * b4.z; acc[3][3] += a0.w * b4.w;
            acc[4][0] += a1.x * b4.x; acc[4][1] += a1.x * b4.y; acc[4][2] += a1.x * b4.z; acc[4][3] += a1.x * b4.w;
            acc[5][0] += a1.y * b4.x; acc[5][1] += a1.y * b4.y; acc[5][2] += a1.y * b4.z; acc[5][3] += a1.y * b4.w;
            acc[6][0] += a1.z * b4.x; acc[6][1] += a1.z * b4.y; acc[6][2] += a1.z * b4.z; acc[6][3] += a1.z * b4.w;
            acc[7][0] += a1.w * b4.x; acc[7][1] += a1.w * b4.y; acc[7][2] += a1.w * b4.z; acc[7][3] += a1.w * b4.w;
        }
    }

    float bf[4];
    #pragma unroll
    for (int j = 0; j < 4; j++) {
        int nn = n0 + tx * 4 + j;
        bf[j] = (nn < VV) ? b_fc[nn] : 0.f;
    }
    #pragma unroll
    for (int i = 0; i < 8; i++) {
        int mm = m0 + ty * 8 + i;
        int tt = mm >> 6, bb = mm & 63;
        size_t obase = ((size_t)bb * TT + tt) * VV;
        #pragma unroll
        for (int j = 0; j < 4; j++) {
            int nn = n0 + tx * 4 + j;
            if (nn < VV) out[obase + nn] = acc[i][j] + bf[j];
        }
    }
}

// ---------------- launch ------------------------------------------------------
extern "C" void kernel_launch(void* const* d_in, const int* in_sizes, int n_in,
                              void* d_out, int out_size)
{
    const float* features = (const float*)d_in[0];
    const void*  captions = d_in[1];
    const float* emb      = (const float*)d_in[2];
    const float* W_ih     = (const float*)d_in[3];
    const float* W_hh     = (const float*)d_in[4];
    const float* b_ih     = (const float*)d_in[5];
    const float* b_hh     = (const float*)d_in[6];
    const float* W_fc     = (const float*)d_in[7];
    const float* b_fc     = (const float*)d_in[8];
    float* out = (float*)d_out;

    init_state<<<(HH * BB + 255) / 256, 256>>>();
    detect_cap<<<1, 256>>>((const int*)captions);

    gemm_xg<<<dim3(GG / 64, MM / 64), 256>>>(features, captions, emb, W_ih, b_ih, b_hh);

    for (int t = 0; t < TT; t++)
        lstm_step<<<HH / 4, 256>>>(t, W_hh);

    gemm_logits<<<dim3((VV + 63) / 64, MM / 128), 256>>>(W_fc, b_fc, out);
}

// round 14
// speedup vs baseline: 2.3806x; 1.1095x over previous
#include <cuda_runtime.h>
#include <cuda_bf16.h>
#include <math.h>

#define BB 64       // batch
#define TT 32       // seq len
#define EE 512      // embed
#define HH 512      // hidden
#define GG 2048     // 4*H
#define VV 10000    // vocab
#define MM 2048     // rows = TT*BB

// ---------------- scratch (device globals; no allocation allowed) -------------
__device__ __align__(16) float g_xg[MM * GG];         // [m][g]  16 MB
__device__ __align__(16) float g_hall[MM * HH];       // [m][j]   4 MB
__device__ __align__(16) float g_h[2][HH * BB];       // double-buffered h, [j][b]
__device__ __align__(16) float g_c[HH * BB];          // cell state [j][b]
__device__ int g_is64;

// ---------------- helpers ----------------------------------------------------
__global__ void init_state() {
    int i = blockIdx.x * blockDim.x + threadIdx.x;
    if (i < HH * BB) { g_h[0][i] = 0.f; g_c[i] = 0.f; }
}

// Detect whether captions buffer is int64 or int32 on device.
__global__ void detect_cap(const int* cap) {
    int nz = 0;
    for (int i = 1 + 2 * threadIdx.x; i < 2 * BB * TT; i += 2 * blockDim.x)
        nz |= (cap[i] != 0);
    nz = __syncthreads_or(nz);
    if (threadIdx.x == 0) g_is64 = (nz == 0);
}

__device__ __forceinline__ void cp16(void* smem, const void* gmem) {
    unsigned s = (unsigned)__cvta_generic_to_shared(smem);
    asm volatile("cp.async.ca.shared.global [%0], [%1], 16;" :: "r"(s), "l"(gmem));
}
__device__ __forceinline__ void cp_commit() { asm volatile("cp.async.commit_group;"); }
template <int N>
__device__ __forceinline__ void cp_wait() { asm volatile("cp.async.wait_group %0;" :: "n"(N)); }

// ---------------- GEMM 1: x_gates (fp32, PROVEN R5 code) ----------------------
__global__ void __launch_bounds__(256) gemm_xg(
    const float* __restrict__ features,
    const void*  __restrict__ captions,
    const float* __restrict__ emb,
    const float* __restrict__ W_ih,
    const float* __restrict__ b_ih,
    const float* __restrict__ b_hh)
{
    __shared__ __align__(16) float As[16][68];
    __shared__ __align__(16) float Bs[16][68];

    const int m0 = blockIdx.y * 64;
    const int n0 = blockIdx.x * 64;
    const int tid = threadIdx.x;
    const int tx = tid & 15, ty = tid >> 4;
    const int lrow = tid >> 2;
    const int lkq  = tid & 3;

    const int m = m0 + lrow;
    const int t = m >> 6, b = m & 63;
    const float* arow;
    if (t == 0) {
        arow = features + (size_t)b * EE;
    } else {
        long long idx;
        if (g_is64) idx = ((const long long*)captions)[b * TT + (t - 1)];
        else        idx = ((const int*)captions)[b * TT + (t - 1)];
        arow = emb + (size_t)idx * EE;
    }
    const float* brow = W_ih + (size_t)(n0 + lrow) * EE;

    float acc[4][4] = {};

    for (int k0 = 0; k0 < EE; k0 += 16) {
        float4 av = *(const float4*)(arow + k0 + lkq * 4);
        float4 bv = *(const float4*)(brow + k0 + lkq * 4);
        __syncthreads();
        As[lkq * 4 + 0][lrow] = av.x; As[lkq * 4 + 1][lrow] = av.y;
        As[lkq * 4 + 2][lrow] = av.z; As[lkq * 4 + 3][lrow] = av.w;
        Bs[lkq * 4 + 0][lrow] = bv.x; Bs[lkq * 4 + 1][lrow] = bv.y;
        Bs[lkq * 4 + 2][lrow] = bv.z; Bs[lkq * 4 + 3][lrow] = bv.w;
        __syncthreads();
        #pragma unroll
        for (int kk = 0; kk < 16; kk++) {
            float4 a4 = *(const float4*)&As[kk][ty * 4];
            float4 b4 = *(const float4*)&Bs[kk][tx * 4];
            acc[0][0] += a4.x * b4.x; acc[0][1] += a4.x * b4.y; acc[0][2] += a4.x * b4.z; acc[0][3] += a4.x * b4.w;
            acc[1][0] += a4.y * b4.x; acc[1][1] += a4.y * b4.y; acc[1][2] += a4.y * b4.z; acc[1][3] += a4.y * b4.w;
            acc[2][0] += a4.z * b4.x; acc[2][1] += a4.z * b4.y; acc[2][2] += a4.z * b4.z; acc[2][3] += a4.z * b4.w;
            acc[3][0] += a4.w * b4.x; acc[3][1] += a4.w * b4.y; acc[3][2] += a4.w * b4.z; acc[3][3] += a4.w * b4.w;
        }
    }

    #pragma unroll
    for (int i = 0; i < 4; i++) {
        int mm = m0 + ty * 4 + i;
        #pragma unroll
        for (int j = 0; j < 4; j++) {
            int nn = n0 + tx * 4 + j;
            g_xg[(size_t)mm * GG + nn] = acc[i][j] + b_ih[nn] + b_hh[nn];
        }
    }
}

// ---------------- LSTM step: 4cols x 1batch thread tile -----------------------
// Same proven pipeline/loaders as R13; ONLY the compute thread-tile is remapped:
// thread = (b = tid&63, gate = tid>>6), owns cols gate*4+q (q=0..3) for batch b.
// Per k4: 4 broadcast LDS.128 (w) + 4 conflict-free LDS.32 (h) + 16 FFMA with
// 4 independent accumulator chains. h smem traffic per warp drops 4x vs R13.
__global__ void __launch_bounds__(256) lstm_step(int t, const float* __restrict__ W_hh)
{
    __shared__ __align__(16) float hs[2][64 * 64];   // 32 KB
    __shared__ __align__(16) float ws[2][16 * 68];   // 8.5 KB  (row c, stride 272B)
    __shared__ __align__(16) float gsh[16 * 68];     // 4.25 KB

    const int tid = threadIdx.x;
    const int jbase = blockIdx.x * 4;

    // --- loader indices (IDENTICAL to R13) ---
    const int lc = tid >> 4;             // 0..15 -> ws row (gate=lc>>2, jl=lc&3)
    const int lb = tid & 15;             // k-quad
    const int lcol = (lc >> 2) * HH + jbase + (lc & 3);
    const float* __restrict__ wsrc = W_hh + (size_t)lcol * HH;

    // --- compute indices (new tile) ---
    const int b  = tid & 63;             // batch
    const int tg = tid >> 6;             // gate 0..3; cols c = tg*4+q

    const float* __restrict__ hin  = g_h[t & 1];
    float* __restrict__ hout = g_h[(t + 1) & 1];
    const float* __restrict__ xgt  = g_xg + (size_t)t * BB * GG;

    // acc init: 4 contiguous cols -> one coalesced float4 from xg
    float4 ainit = *(const float4*)&xgt[(size_t)b * GG + tg * HH + jbase];
    float acc0 = ainit.x, acc1 = ainit.y, acc2 = ainit.z, acc3 = ainit.w;

    // prefetch chunk 0 (h + W)
    #pragma unroll
    for (int r = 0; r < 4; r++) {
        int f = tid + r * 256;
        int k = f >> 4, bq = f & 15;
        cp16(&hs[0][k * 64 + bq * 4], &hin[(size_t)k * BB + bq * 4]);
    }
    cp16(&ws[0][lc * 68 + lb * 4], wsrc + lb * 4);
    cp_commit();

    #pragma unroll
    for (int kc = 0; kc < 8; kc++) {
        if (kc < 7) {
            #pragma unroll
            for (int r = 0; r < 4; r++) {
                int f = tid + r * 256;
                int k = f >> 4, bq = f & 15;
                cp16(&hs[(kc + 1) & 1][k * 64 + bq * 4],
                     &hin[(size_t)((kc + 1) * 64 + k) * BB + bq * 4]);
            }
            cp16(&ws[(kc + 1) & 1][lc * 68 + lb * 4], wsrc + (kc + 1) * 64 + lb * 4);
            cp_commit();
            cp_wait<1>();
        } else {
            cp_wait<0>();
        }
        __syncthreads();

        const float* hc = hs[kc & 1];
        const float* w0p = &ws[kc & 1][(tg * 4 + 0) * 68];
        const float* w1p = &ws[kc & 1][(tg * 4 + 1) * 68];
        const float* w2p = &ws[kc & 1][(tg * 4 + 2) * 68];
        const float* w3p = &ws[kc & 1][(tg * 4 + 3) * 68];
        #pragma unroll
        for (int k4 = 0; k4 < 16; k4++) {
            float4 w0 = *(const float4*)&w0p[k4 * 4];
            float4 w1 = *(const float4*)&w1p[k4 * 4];
            float4 w2 = *(const float4*)&w2p[k4 * 4];
            float4 w3 = *(const float4*)&w3p[k4 * 4];
            {
                float h0 = hc[(k4 * 4 + 0) * 64 + b];
                acc0 += h0 * w0.x; acc1 += h0 * w1.x; acc2 += h0 * w2.x; acc3 += h0 * w3.x;
            }
            {
                float h1 = hc[(k4 * 4 + 1) * 64 + b];
                acc0 += h1 * w0.y; acc1 += h1 * w1.y; acc2 += h1 * w2.y; acc3 += h1 * w3.y;
            }
            {
                float h2 = hc[(k4 * 4 + 2) * 64 + b];
                acc0 += h2 * w0.z; acc1 += h2 * w1.z; acc2 += h2 * w2.z; acc3 += h2 * w3.z;
            }
            {
                float h3 = hc[(k4 * 4 + 3) * 64 + b];
                acc0 += h3 * w0.w; acc1 += h3 * w1.w; acc2 += h3 * w2.w; acc3 += h3 * w3.w;
            }
        }
        __syncthreads();
    }

    // stage gates: thread holds cols tg*4+q for batch b
    gsh[(tg * 4 + 0) * 68 + b] = acc0;
    gsh[(tg * 4 + 1) * 68 + b] = acc1;
    gsh[(tg * 4 + 2) * 68 + b] = acc2;
    gsh[(tg * 4 + 3) * 68 + b] = acc3;
    __syncthreads();

    // nonlinearity (unchanged mapping): thread -> (bnl, jl); cc = gate*4 + jl
    const int bnl = tid & 63, jl = tid >> 6;
    const float iv = gsh[(0  + jl) * 68 + bnl];
    const float fv = gsh[(4  + jl) * 68 + bnl];
    const float gv = gsh[(8  + jl) * 68 + bnl];
    const float ov = gsh[(12 + jl) * 68 + bnl];
    const int j = jbase + jl;

    float c_old = g_c[(size_t)j * BB + bnl];
    float si = 1.f / (1.f + expf(-iv));
    float sf = 1.f / (1.f + expf(-fv));
    float so = 1.f / (1.f + expf(-ov));
    float tg_ = tanhf(gv);
    float cn = sf * c_old + si * tg_;
    float hn = so * tanhf(cn);
    g_c[(size_t)j * BB + bnl] = cn;
    hout[(size_t)j * BB + bnl] = hn;
    g_hall[((size_t)t * BB + bnl) * HH + j] = hn;
}

// ---------------- GEMM 2: logits fp32 128x64 (PROVEN R5 code) -----------------
__global__ void __launch_bounds__(256) gemm_logits(
    const float* __restrict__ W_fc,
    const float* __restrict__ b_fc,
    float* __restrict__ out)
{
    __shared__ __align__(16) float As[16][132];
    __shared__ __align__(16) float Bs[16][68];

    const int m0 = blockIdx.y * 128;
    const int n0 = blockIdx.x * 64;
    const int tid = threadIdx.x;
    const int tx = tid & 15, ty = tid >> 4;
    const int lrow = tid >> 2;
    const int lkq  = tid & 3;

    const float* a0p = g_hall + (size_t)(m0 + lrow) * HH + lkq * 4;
    const float* a1p = g_hall + (size_t)(m0 + lrow + 64) * HH + lkq * 4;
    int nb = n0 + lrow; if (nb >= VV) nb = VV - 1;
    const float* bp = W_fc + (size_t)nb * HH + lkq * 4;

    float acc[8][4] = {};

    for (int k0 = 0; k0 < HH; k0 += 16) {
        float4 av0 = *(const float4*)(a0p + k0);
        float4 av1 = *(const float4*)(a1p + k0);
        float4 bv  = *(const float4*)(bp + k0);
        __syncthreads();
        As[lkq * 4 + 0][lrow] = av0.x; As[lkq * 4 + 1][lrow] = av0.y;
        As[lkq * 4 + 2][lrow] = av0.z; As[lkq * 4 + 3][lrow] = av0.w;
        As[lkq * 4 + 0][lrow + 64] = av1.x; As[lkq * 4 + 1][lrow + 64] = av1.y;
        As[lkq * 4 + 2][lrow + 64] = av1.z; As[lkq * 4 + 3][lrow + 64] = av1.w;
        Bs[lkq * 4 + 0][lrow] = bv.x; Bs[lkq * 4 + 1][lrow] = bv.y;
        Bs[lkq * 4 + 2][lrow] = bv.z; Bs[lkq * 4 + 3][lrow] = bv.w;
        __syncthreads();
        #pragma unroll
        for (int kk = 0; kk < 16; kk++) {
            float4 a0 = *(const float4*)&As[kk][ty * 8];
            float4 a1 = *(const float4*)&As[kk][ty * 8 + 4];
            float4 b4 = *(const float4*)&Bs[kk][tx * 4];
            acc[0][0] += a0.x * b4.x; acc[0][1] += a0.x * b4.y; acc[0][2] += a0.x * b4.z; acc[0][3] += a0.x * b4.w;
            acc[1][0] += a0.y * b4.x; acc[1][1] += a0.y * b4.y; acc[1][2] += a0.y * b4.z; acc[1][3] += a0.y * b4.w;
            acc[2][0] += a0.z * b4.x; acc[2][1] += a0.z * b4.y; acc[2][2] += a0.z * b4.z; acc[2][3] += a0.z * b4.w;
            acc[3][0] += a0.w * b4.x; acc[3][1] += a0.w * b4.y; acc[3][2] += a0.w * b4.z; acc[3][3] += a0.w * b4.w;
            acc[4][0] += a1.x * b4.x; acc[4][1] += a1.x * b4.y; acc[4][2] += a1.x * b4.z; acc[4][3] += a1.x * b4.w;
            acc[5][0] += a1.y * b4.x; acc[5][1] += a1.y * b4.y; acc[5][2] += a1.y * b4.z; acc[5][3] += a1.y * b4.w;
            acc[6][0] += a1.z * b4.x; acc[6][1] += a1.z * b4.y; acc[6][2] += a1.z * b4.z; acc[6][3] += a1.z * b4.w;
            acc[7][0] += a1.w * b4.x; acc[7][1] += a1.w * b4.y; acc[7][2] += a1.w * b4.z; acc[7][3] += a1.w * b4.w;
        }
    }

    float bf[4];
    #pragma unroll
    for (int j = 0; j < 4; j++) {
        int nn = n0 + tx * 4 + j;
        bf[j] = (nn < VV) ? b_fc[nn] : 0.f;
    }
    #pragma unroll
    for (int i = 0; i < 8; i++) {
        int mm = m0 + ty * 8 + i;
        int tt = mm >> 6, bb = mm & 63;
        size_t obase = ((size_t)bb * TT + tt) * VV;
        #pragma unroll
        for (int j = 0; j < 4; j++) {
            int nn = n0 + tx * 4 + j;
            if (nn < VV) out[obase + nn] = acc[i][j] + bf[j];
        }
    }
}

// ---------------- launch ------------------------------------------------------
extern "C" void kernel_launch(void* const* d_in, const int* in_sizes, int n_in,
                              void* d_out, int out_size)
{
    const float* features = (const float*)d_in[0];
    const void*  captions = d_in[1];
    const float* emb      = (const float*)d_in[2];
    const float* W_ih     = (const float*)d_in[3];
    const float* W_hh     = (const float*)d_in[4];
    const float* b_ih     = (const float*)d_in[5];
    const float* b_hh     = (const float*)d_in[6];
    const float* W_fc     = (const float*)d_in[7];
    const float* b_fc     = (const float*)d_in[8];
    float* out = (float*)d_out;

    init_state<<<(HH * BB + 255) / 256, 256>>>();
    detect_cap<<<1, 256>>>((const int*)captions);

    gemm_xg<<<dim3(GG / 64, MM / 64), 256>>>(features, captions, emb, W_ih, b_ih, b_hh);

    for (int t = 0; t < TT; t++)
        lstm_step<<<HH / 4, 256>>>(t, W_hh);

    gemm_logits<<<dim3((VV + 63) / 64, MM / 128), 256>>>(W_fc, b_fc, out);
}

// round 15
// speedup vs baseline: 2.4383x; 1.0242x over previous
#include <cuda_runtime.h>
#include <cuda_bf16.h>
#include <math.h>

#define BB 64       // batch
#define TT 32       // seq len
#define EE 512      // embed
#define HH 512      // hidden
#define GG 2048     // 4*H
#define VV 10000    // vocab
#define MM 2048     // rows = TT*BB

// ---------------- scratch (device globals; no allocation allowed) -------------
__device__ __align__(16) float g_xg[MM * GG];         // [m][g]  16 MB
__device__ __align__(16) float g_hall[MM * HH];       // [m][j]   4 MB
__device__ __align__(16) float g_h[2][HH * BB];       // double-buffered h, [j][b]
__device__ __align__(16) float g_c[HH * BB];          // cell state [j][b]
__device__ int g_is64;

// ---------------- helpers ----------------------------------------------------
__global__ void init_state() {
    int i = blockIdx.x * blockDim.x + threadIdx.x;
    if (i < HH * BB) { g_h[0][i] = 0.f; g_c[i] = 0.f; }
}

// Detect whether captions buffer is int64 or int32 on device.
__global__ void detect_cap(const int* cap) {
    int nz = 0;
    for (int i = 1 + 2 * threadIdx.x; i < 2 * BB * TT; i += 2 * blockDim.x)
        nz |= (cap[i] != 0);
    nz = __syncthreads_or(nz);
    if (threadIdx.x == 0) g_is64 = (nz == 0);
}

__device__ __forceinline__ void cp16(void* smem, const void* gmem) {
    unsigned s = (unsigned)__cvta_generic_to_shared(smem);
    asm volatile("cp.async.ca.shared.global [%0], [%1], 16;" :: "r"(s), "l"(gmem));
}
__device__ __forceinline__ void cp_commit() { asm volatile("cp.async.commit_group;"); }
template <int N>
__device__ __forceinline__ void cp_wait() { asm volatile("cp.async.wait_group %0;" :: "n"(N)); }

// packed f32x2 helpers (PTX ISA 8.6, sm_100+)
__device__ __forceinline__ unsigned long long ffma2(unsigned long long a,
                                                    unsigned long long b,
                                                    unsigned long long c) {
    unsigned long long d;
    asm("fma.rn.f32x2 %0, %1, %2, %3;" : "=l"(d) : "l"(a), "l"(b), "l"(c));
    return d;
}
__device__ __forceinline__ unsigned long long splat2(float x) {
    unsigned long long r;
    asm("mov.b64 %0, {%1, %1};" : "=l"(r) : "f"(x));
    return r;
}

// ---------------- GEMM 1: x_gates (fp32, PROVEN R5 code) ----------------------
__global__ void __launch_bounds__(256) gemm_xg(
    const float* __restrict__ features,
    const void*  __restrict__ captions,
    const float* __restrict__ emb,
    const float* __restrict__ W_ih,
    const float* __restrict__ b_ih,
    const float* __restrict__ b_hh)
{
    __shared__ __align__(16) float As[16][68];
    __shared__ __align__(16) float Bs[16][68];

    const int m0 = blockIdx.y * 64;
    const int n0 = blockIdx.x * 64;
    const int tid = threadIdx.x;
    const int tx = tid & 15, ty = tid >> 4;
    const int lrow = tid >> 2;
    const int lkq  = tid & 3;

    const int m = m0 + lrow;
    const int t = m >> 6, b = m & 63;
    const float* arow;
    if (t == 0) {
        arow = features + (size_t)b * EE;
    } else {
        long long idx;
        if (g_is64) idx = ((const long long*)captions)[b * TT + (t - 1)];
        else        idx = ((const int*)captions)[b * TT + (t - 1)];
        arow = emb + (size_t)idx * EE;
    }
    const float* brow = W_ih + (size_t)(n0 + lrow) * EE;

    float acc[4][4] = {};

    for (int k0 = 0; k0 < EE; k0 += 16) {
        float4 av = *(const float4*)(arow + k0 + lkq * 4);
        float4 bv = *(const float4*)(brow + k0 + lkq * 4);
        __syncthreads();
        As[lkq * 4 + 0][lrow] = av.x; As[lkq * 4 + 1][lrow] = av.y;
        As[lkq * 4 + 2][lrow] = av.z; As[lkq * 4 + 3][lrow] = av.w;
        Bs[lkq * 4 + 0][lrow] = bv.x; Bs[lkq * 4 + 1][lrow] = bv.y;
        Bs[lkq * 4 + 2][lrow] = bv.z; Bs[lkq * 4 + 3][lrow] = bv.w;
        __syncthreads();
        #pragma unroll
        for (int kk = 0; kk < 16; kk++) {
            float4 a4 = *(const float4*)&As[kk][ty * 4];
            float4 b4 = *(const float4*)&Bs[kk][tx * 4];
            acc[0][0] += a4.x * b4.x; acc[0][1] += a4.x * b4.y; acc[0][2] += a4.x * b4.z; acc[0][3] += a4.x * b4.w;
            acc[1][0] += a4.y * b4.x; acc[1][1] += a4.y * b4.y; acc[1][2] += a4.y * b4.z; acc[1][3] += a4.y * b4.w;
            acc[2][0] += a4.z * b4.x; acc[2][1] += a4.z * b4.y; acc[2][2] += a4.z * b4.z; acc[2][3] += a4.z * b4.w;
            acc[3][0] += a4.w * b4.x; acc[3][1] += a4.w * b4.y; acc[3][2] += a4.w * b4.z; acc[3][3] += a4.w * b4.w;
        }
    }

    #pragma unroll
    for (int i = 0; i < 4; i++) {
        int mm = m0 + ty * 4 + i;
        #pragma unroll
        for (int j = 0; j < 4; j++) {
            int nn = n0 + tx * 4 + j;
            g_xg[(size_t)mm * GG + nn] = acc[i][j] + b_ih[nn] + b_hh[nn];
        }
    }
}

// ---------------- LSTM step (PROVEN R14 code) ----------------------------------
__global__ void __launch_bounds__(256) lstm_step(int t, const float* __restrict__ W_hh)
{
    __shared__ __align__(16) float hs[2][64 * 64];   // 32 KB
    __shared__ __align__(16) float ws[2][16 * 68];   // 8.5 KB  (row c, stride 272B)
    __shared__ __align__(16) float gsh[16 * 68];     // 4.25 KB

    const int tid = threadIdx.x;
    const int jbase = blockIdx.x * 4;

    const int lc = tid >> 4;             // 0..15 -> ws row (gate=lc>>2, jl=lc&3)
    const int lb = tid & 15;             // k-quad
    const int lcol = (lc >> 2) * HH + jbase + (lc & 3);
    const float* __restrict__ wsrc = W_hh + (size_t)lcol * HH;

    const int b  = tid & 63;             // batch
    const int tg = tid >> 6;             // gate 0..3; cols c = tg*4+q

    const float* __restrict__ hin  = g_h[t & 1];
    float* __restrict__ hout = g_h[(t + 1) & 1];
    const float* __restrict__ xgt  = g_xg + (size_t)t * BB * GG;

    float4 ainit = *(const float4*)&xgt[(size_t)b * GG + tg * HH + jbase];
    float acc0 = ainit.x, acc1 = ainit.y, acc2 = ainit.z, acc3 = ainit.w;

    #pragma unroll
    for (int r = 0; r < 4; r++) {
        int f = tid + r * 256;
        int k = f >> 4, bq = f & 15;
        cp16(&hs[0][k * 64 + bq * 4], &hin[(size_t)k * BB + bq * 4]);
    }
    cp16(&ws[0][lc * 68 + lb * 4], wsrc + lb * 4);
    cp_commit();

    #pragma unroll
    for (int kc = 0; kc < 8; kc++) {
        if (kc < 7) {
            #pragma unroll
            for (int r = 0; r < 4; r++) {
                int f = tid + r * 256;
                int k = f >> 4, bq = f & 15;
                cp16(&hs[(kc + 1) & 1][k * 64 + bq * 4],
                     &hin[(size_t)((kc + 1) * 64 + k) * BB + bq * 4]);
            }
            cp16(&ws[(kc + 1) & 1][lc * 68 + lb * 4], wsrc + (kc + 1) * 64 + lb * 4);
            cp_commit();
            cp_wait<1>();
        } else {
            cp_wait<0>();
        }
        __syncthreads();

        const float* hc = hs[kc & 1];
        const float* w0p = &ws[kc & 1][(tg * 4 + 0) * 68];
        const float* w1p = &ws[kc & 1][(tg * 4 + 1) * 68];
        const float* w2p = &ws[kc & 1][(tg * 4 + 2) * 68];
        const float* w3p = &ws[kc & 1][(tg * 4 + 3) * 68];
        #pragma unroll
        for (int k4 = 0; k4 < 16; k4++) {
            float4 w0 = *(const float4*)&w0p[k4 * 4];
            float4 w1 = *(const float4*)&w1p[k4 * 4];
            float4 w2 = *(const float4*)&w2p[k4 * 4];
            float4 w3 = *(const float4*)&w3p[k4 * 4];
            {
                float h0 = hc[(k4 * 4 + 0) * 64 + b];
                acc0 += h0 * w0.x; acc1 += h0 * w1.x; acc2 += h0 * w2.x; acc3 += h0 * w3.x;
            }
            {
                float h1 = hc[(k4 * 4 + 1) * 64 + b];
                acc0 += h1 * w0.y; acc1 += h1 * w1.y; acc2 += h1 * w2.y; acc3 += h1 * w3.y;
            }
            {
                float h2 = hc[(k4 * 4 + 2) * 64 + b];
                acc0 += h2 * w0.z; acc1 += h2 * w1.z; acc2 += h2 * w2.z; acc3 += h2 * w3.z;
            }
            {
                float h3 = hc[(k4 * 4 + 3) * 64 + b];
                acc0 += h3 * w0.w; acc1 += h3 * w1.w; acc2 += h3 * w2.w; acc3 += h3 * w3.w;
            }
        }
        __syncthreads();
    }

    gsh[(tg * 4 + 0) * 68 + b] = acc0;
    gsh[(tg * 4 + 1) * 68 + b] = acc1;
    gsh[(tg * 4 + 2) * 68 + b] = acc2;
    gsh[(tg * 4 + 3) * 68 + b] = acc3;
    __syncthreads();

    const int bnl = tid & 63, jl = tid >> 6;
    const float iv = gsh[(0  + jl) * 68 + bnl];
    const float fv = gsh[(4  + jl) * 68 + bnl];
    const float gv = gsh[(8  + jl) * 68 + bnl];
    const float ov = gsh[(12 + jl) * 68 + bnl];
    const int j = jbase + jl;

    float c_old = g_c[(size_t)j * BB + bnl];
    float si = 1.f / (1.f + expf(-iv));
    float sf = 1.f / (1.f + expf(-fv));
    float so = 1.f / (1.f + expf(-ov));
    float tg_ = tanhf(gv);
    float cn = sf * c_old + si * tg_;
    float hn = so * tanhf(cn);
    g_c[(size_t)j * BB + bnl] = cn;
    hout[(size_t)j * BB + bnl] = hn;
    g_hall[((size_t)t * BB + bnl) * HH + j] = hn;
}

// ---------------- GEMM 2: logits fp32 128x64 + packed FFMA2 -------------------
// Same tile/loaders/epilogue as proven R5/R14 kernel; inner product uses
// fma.rn.f32x2 packed over the m dimension (a-pairs are contiguous in As).
// Arithmetic is bit-identical to the scalar version (FFMA2 = 2 indep FFMAs).
__global__ void __launch_bounds__(256) gemm_logits(
    const float* __restrict__ W_fc,
    const float* __restrict__ b_fc,
    float* __restrict__ out)
{
    __shared__ __align__(16) float As[16][132];
    __shared__ __align__(16) float Bs[16][68];

    const int m0 = blockIdx.y * 128;
    const int n0 = blockIdx.x * 64;
    const int tid = threadIdx.x;
    const int tx = tid & 15, ty = tid >> 4;
    const int lrow = tid >> 2;
    const int lkq  = tid & 3;

    const float* a0p = g_hall + (size_t)(m0 + lrow) * HH + lkq * 4;
    const float* a1p = g_hall + (size_t)(m0 + lrow + 64) * HH + lkq * 4;
    int nb = n0 + lrow; if (nb >= VV) nb = VV - 1;
    const float* bp = W_fc + (size_t)nb * HH + lkq * 4;

    // packed accumulators: accp[p][j] holds rows (2p, 2p+1) of the 8-row tile
    unsigned long long accp[4][4] = {};

    for (int k0 = 0; k0 < HH; k0 += 16) {
        float4 av0 = *(const float4*)(a0p + k0);
        float4 av1 = *(const float4*)(a1p + k0);
        float4 bv  = *(const float4*)(bp + k0);
        __syncthreads();
        As[lkq * 4 + 0][lrow] = av0.x; As[lkq * 4 + 1][lrow] = av0.y;
        As[lkq * 4 + 2][lrow] = av0.z; As[lkq * 4 + 3][lrow] = av0.w;
        As[lkq * 4 + 0][lrow + 64] = av1.x; As[lkq * 4 + 1][lrow + 64] = av1.y;
        As[lkq * 4 + 2][lrow + 64] = av1.z; As[lkq * 4 + 3][lrow + 64] = av1.w;
        Bs[lkq * 4 + 0][lrow] = bv.x; Bs[lkq * 4 + 1][lrow] = bv.y;
        Bs[lkq * 4 + 2][lrow] = bv.z; Bs[lkq * 4 + 3][lrow] = bv.w;
        __syncthreads();
        #pragma unroll
        for (int kk = 0; kk < 16; kk++) {
            ulonglong2 a01 = *(const ulonglong2*)&As[kk][ty * 8];       // pairs 0,1
            ulonglong2 a23 = *(const ulonglong2*)&As[kk][ty * 8 + 4];   // pairs 2,3
            float4 b4 = *(const float4*)&Bs[kk][tx * 4];
            unsigned long long bs0 = splat2(b4.x);
            unsigned long long bs1 = splat2(b4.y);
            unsigned long long bs2 = splat2(b4.z);
            unsigned long long bs3 = splat2(b4.w);
            accp[0][0] = ffma2(a01.x, bs0, accp[0][0]);
            accp[0][1] = ffma2(a01.x, bs1, accp[0][1]);
            accp[0][2] = ffma2(a01.x, bs2, accp[0][2]);
            accp[0][3] = ffma2(a01.x, bs3, accp[0][3]);
            accp[1][0] = ffma2(a01.y, bs0, accp[1][0]);
            accp[1][1] = ffma2(a01.y, bs1, accp[1][1]);
            accp[1][2] = ffma2(a01.y, bs2, accp[1][2]);
            accp[1][3] = ffma2(a01.y, bs3, accp[1][3]);
            accp[2][0] = ffma2(a23.x, bs0, accp[2][0]);
            accp[2][1] = ffma2(a23.x, bs1, accp[2][1]);
            accp[2][2] = ffma2(a23.x, bs2, accp[2][2]);
            accp[2][3] = ffma2(a23.x, bs3, accp[2][3]);
            accp[3][0] = ffma2(a23.y, bs0, accp[3][0]);
            accp[3][1] = ffma2(a23.y, bs1, accp[3][1]);
            accp[3][2] = ffma2(a23.y, bs2, accp[3][2]);
            accp[3][3] = ffma2(a23.y, bs3, accp[3][3]);
        }
    }

    float bf[4];
    #pragma unroll
    for (int j = 0; j < 4; j++) {
        int nn = n0 + tx * 4 + j;
        bf[j] = (nn < VV) ? b_fc[nn] : 0.f;
    }
    #pragma unroll
    for (int p = 0; p < 4; p++) {
        float2 v[4];
        #pragma unroll
        for (int j = 0; j < 4; j++) v[j] = *(float2*)&accp[p][j];
        #pragma unroll
        for (int half = 0; half < 2; half++) {
            int mm = m0 + ty * 8 + 2 * p + half;
            int tt = mm >> 6, bb = mm & 63;
            size_t obase = ((size_t)bb * TT + tt) * VV;
            #pragma unroll
            for (int j = 0; j < 4; j++) {
                int nn = n0 + tx * 4 + j;
                float val = half ? v[j].y : v[j].x;
                if (nn < VV) out[obase + nn] = val + bf[j];
            }
        }
    }
}

// ---------------- launch ------------------------------------------------------
extern "C" void kernel_launch(void* const* d_in, const int* in_sizes, int n_in,
                              void* d_out, int out_size)
{
    const float* features = (const float*)d_in[0];
    const void*  captions = d_in[1];
    const float* emb      = (const float*)d_in[2];
    const float* W_ih     = (const float*)d_in[3];
    const float* W_hh     = (const float*)d_in[4];
    const float* b_ih     = (const float*)d_in[5];
    const float* b_hh     = (const float*)d_in[6];
    const float* W_fc     = (const float*)d_in[7];
    const float* b_fc     = (const float*)d_in[8];
    float* out = (float*)d_out;

    init_state<<<(HH * BB + 255) / 256, 256>>>();
    detect_cap<<<1, 256>>>((const int*)captions);

    gemm_xg<<<dim3(GG / 64, MM / 64), 256>>>(features, captions, emb, W_ih, b_ih, b_hh);

    for (int t = 0; t < TT; t++)
        lstm_step<<<HH / 4, 256>>>(t, W_hh);

    gemm_logits<<<dim3((VV + 63) / 64, MM / 128), 256>>>(W_fc, b_fc, out);
}